// round 14
// baseline (speedup 1.0000x reference)
#include <cuda_runtime.h>
#include <cuda_fp16.h>
#include <math.h>
#include <stdint.h>

// Problem constants
#define B_   4
#define T_   2048
#define S_   2048
#define DQ_  512
#define DKV_ 1024
#define H_   8
#define HD_  64
#define NSB  16            // number of s-blocks (S_/128)

// Scratch buffers (allocation-free: __device__ globals)
__device__ __half g_Qh[B_ * T_ * DQ_];              // [B,T,512] half
__device__ __half g_Kh[B_ * S_ * DQ_];              // [B,S,512] half
__device__ __half g_Vt[B_ * H_ * HD_ * (size_t)S_]; // V transposed: [b,h,d,s] half
__device__ float  g_ctx[B_ * T_ * DQ_];
__device__ float  g_psum[B_ * H_ * T_ * NSB];       // per-(row, s-block) exp sums
__device__ float  g_inv[B_ * H_ * T_];              // 1 / row sum

// ---------------------------------------------------------------------------
// Helpers
// ---------------------------------------------------------------------------
__device__ __forceinline__ uint32_t f2tf32(float f) {
    uint32_t r;
    asm("cvt.rna.tf32.f32 %0, %1;" : "=r"(r) : "f"(f));
    return r;
}
__device__ __forceinline__ uint32_t ldtf(const float* p) { return f2tf32(*p); }

__device__ __forceinline__ uint32_t pack_h2(float lo, float hi) {
    uint32_t r;
    asm("cvt.rn.f16x2.f32 %0, %1, %2;" : "=r"(r) : "f"(hi), "f"(lo));
    return r;
}

__device__ __forceinline__ void mma_tf32(float d[4],
                                         uint32_t a0, uint32_t a1, uint32_t a2, uint32_t a3,
                                         uint32_t b0, uint32_t b1) {
    asm volatile(
        "mma.sync.aligned.m16n8k8.row.col.f32.tf32.tf32.f32 "
        "{%0,%1,%2,%3}, {%4,%5,%6,%7}, {%8,%9}, {%0,%1,%2,%3};\n"
        : "+f"(d[0]), "+f"(d[1]), "+f"(d[2]), "+f"(d[3])
        : "r"(a0), "r"(a1), "r"(a2), "r"(a3), "r"(b0), "r"(b1));
}

__device__ __forceinline__ void mma_f16(float d[4],
                                        uint32_t a0, uint32_t a1, uint32_t a2, uint32_t a3,
                                        uint32_t b0, uint32_t b1) {
    asm volatile(
        "mma.sync.aligned.m16n8k16.row.col.f32.f16.f16.f32 "
        "{%0,%1,%2,%3}, {%4,%5,%6,%7}, {%8,%9}, {%0,%1,%2,%3};\n"
        : "+f"(d[0]), "+f"(d[1]), "+f"(d[2]), "+f"(d[3])
        : "r"(a0), "r"(a1), "r"(a2), "r"(a3), "r"(b0), "r"(b1));
}

__device__ __forceinline__ void cp_async16(uint32_t s, const void* g) {
    asm volatile("cp.async.cg.shared.global [%0], [%1], 16;\n" :: "r"(s), "l"(g));
}
__device__ __forceinline__ void cp_commit() { asm volatile("cp.async.commit_group;\n" ::: "memory"); }
__device__ __forceinline__ void cp_wait0()  { asm volatile("cp.async.wait_group 0;\n" ::: "memory"); }

// ---------------------------------------------------------------------------
// Projections:  C[M,N] = A[M,K] @ W[K,N] + bias[N]   (tf32 mainloop, proven)
// MODE 0: fp32 out. MODE 1: half out, normal layout. MODE 2: half out, Vt layout.
// ---------------------------------------------------------------------------
template <int MODE>
__global__ __launch_bounds__(128, 4) void gemm_bias_tc(
    const float* __restrict__ A, const float* __restrict__ W,
    const float* __restrict__ bias, void* __restrict__ Cout,
    int M, int N, int K)
{
    extern __shared__ float dsm[];
    float* As = dsm;                    // [2][128][36]
    float* Bs = dsm + 2 * 128 * 36;     // [2][32][68]
    const uint32_t abase = (uint32_t)__cvta_generic_to_shared(As);
    const uint32_t bbase = (uint32_t)__cvta_generic_to_shared(Bs);

    const int tid = threadIdx.x;
    const int wid = tid >> 5, lane = tid & 31;
    const int g = lane >> 2, tg = lane & 3;
    const int bm = blockIdx.y * 128, bn = blockIdx.x * 64;
    const int wm = (wid >> 1) * 64, wn = (wid & 1) * 32;

    float acc[4][4][4];
    #pragma unroll
    for (int mt = 0; mt < 4; mt++)
        #pragma unroll
        for (int nt = 0; nt < 4; nt++)
            #pragma unroll
            for (int r = 0; r < 4; r++) acc[mt][nt][r] = 0.f;

    auto load_stage = [&](int buf, int k0) {
        uint32_t ab = abase + (uint32_t)buf * 128 * 36 * 4;
        #pragma unroll
        for (int i = tid; i < 128 * 8; i += 128) {
            int r = i >> 3, seg = i & 7;
            cp_async16(ab + (r * 36 + seg * 4) * 4,
                       A + (size_t)(bm + r) * K + k0 + seg * 4);
        }
        uint32_t bb = bbase + (uint32_t)buf * 32 * 68 * 4;
        #pragma unroll
        for (int i = tid; i < 32 * 16; i += 128) {
            int r = i >> 4, seg = i & 15;
            cp_async16(bb + (r * 68 + seg * 4) * 4,
                       W + (size_t)(k0 + r) * N + bn + seg * 4);
        }
        cp_commit();
    };

    load_stage(0, 0);
    int buf = 0;
    for (int k0 = 0; k0 < K; k0 += 32, buf ^= 1) {
        cp_wait0();
        __syncthreads();
        if (k0 + 32 < K) load_stage(buf ^ 1, k0 + 32);

        const float* Ab = As + buf * 128 * 36;
        const float* Bb = Bs + buf * 32 * 68;
        #pragma unroll
        for (int ks = 0; ks < 4; ks++) {
            const int kk = ks * 8;
            uint32_t a[4][4], bf[4][2];
            #pragma unroll
            for (int mt = 0; mt < 4; mt++) {
                int mr = wm + mt * 16;
                a[mt][0] = ldtf(Ab + (mr + g) * 36 + kk + tg);
                a[mt][1] = ldtf(Ab + (mr + g + 8) * 36 + kk + tg);
                a[mt][2] = ldtf(Ab + (mr + g) * 36 + kk + tg + 4);
                a[mt][3] = ldtf(Ab + (mr + g + 8) * 36 + kk + tg + 4);
            }
            #pragma unroll
            for (int nt = 0; nt < 4; nt++) {
                int nc = wn + nt * 8 + g;
                bf[nt][0] = ldtf(Bb + (kk + tg) * 68 + nc);
                bf[nt][1] = ldtf(Bb + (kk + tg + 4) * 68 + nc);
            }
            #pragma unroll
            for (int mt = 0; mt < 4; mt++)
                #pragma unroll
                for (int nt = 0; nt < 4; nt++)
                    mma_tf32(acc[mt][nt], a[mt][0], a[mt][1], a[mt][2], a[mt][3],
                             bf[nt][0], bf[nt][1]);
        }
    }

    #pragma unroll
    for (int mt = 0; mt < 4; mt++) {
        #pragma unroll
        for (int nt = 0; nt < 4; nt++) {
            int n0 = bn + wn + nt * 8 + tg * 2;
            float b0v = bias[n0], b1v = bias[n0 + 1];
            int r0 = bm + wm + mt * 16 + g;
            float v00 = acc[mt][nt][0] + b0v, v01 = acc[mt][nt][1] + b1v;
            float v10 = acc[mt][nt][2] + b0v, v11 = acc[mt][nt][3] + b1v;
            if (MODE == 0) {
                float* C = (float*)Cout;
                C[(size_t)r0 * N + n0]           = v00;
                C[(size_t)r0 * N + n0 + 1]       = v01;
                C[(size_t)(r0 + 8) * N + n0]     = v10;
                C[(size_t)(r0 + 8) * N + n0 + 1] = v11;
            } else if (MODE == 1) {
                __half* C = (__half*)Cout;
                C[(size_t)r0 * N + n0]           = __float2half(v00);
                C[(size_t)r0 * N + n0 + 1]       = __float2half(v01);
                C[(size_t)(r0 + 8) * N + n0]     = __float2half(v10);
                C[(size_t)(r0 + 8) * N + n0 + 1] = __float2half(v11);
            } else {
                __half* C = (__half*)Cout;
                int h0 = n0 >> 6, d0 = n0 & 63;
                int b0i = r0 >> 11, t0i = r0 & 2047;
                size_t base0 = ((size_t)(b0i * 8 + h0) * 64 + d0) * 2048;
                C[base0 + t0i]            = __float2half(v00);
                C[base0 + 2048 + t0i]     = __float2half(v01);
                C[base0 + t0i + 8]        = __float2half(v10);
                C[base0 + 2048 + t0i + 8] = __float2half(v11);
            }
        }
    }
}

// ---------------------------------------------------------------------------
// Scores (fp16 mma) + fused exp: E[b,h,t,s] = exp((Q.K)/8 + mask), kpm==0 -> 0.
// Row sums via SMEM TRANSPOSE (no shfl): lane partial -> Ps[r][lane];
// then 128 threads reduce one row each with 8x LDS.128.
// ---------------------------------------------------------------------------
#define EPAD 136
#define PPAD 36

__global__ __launch_bounds__(256, 2) void score_h(
    const __half* __restrict__ Q, const __half* __restrict__ Kp,
    const float* __restrict__ attn_mask, const int* __restrict__ kpm,
    float* __restrict__ attn, float* __restrict__ psum)
{
    extern __shared__ float dsm[];
    __half* Qs = (__half*)dsm;            // [128][72] half
    __half* Ks = Qs + 128 * 72;           // [128][72] half
    float*  Es = dsm;                     // [128][136] fp32 (overlays Q/K)
    float*  Ps = dsm + 128 * EPAD;        // [128][36] fp32 lane partials
    const uint32_t qbase = (uint32_t)__cvta_generic_to_shared(Qs);
    const uint32_t kbase = (uint32_t)__cvta_generic_to_shared(Ks);

    const int tid = threadIdx.x;
    const int wid = tid >> 5, lane = tid & 31;
    const int g = lane >> 2, tg = lane & 3;
    const int bh = blockIdx.z;
    const int b = bh >> 3, h = bh & 7;
    const int t0 = blockIdx.y * 128, s0 = blockIdx.x * 128;
    const int wm = (wid >> 2) * 64, wn = (wid & 3) * 32;

    #pragma unroll
    for (int i = tid; i < 128 * 8; i += 256) {
        int r = i >> 3, seg = i & 7;
        cp_async16(qbase + (r * 72 + seg * 8) * 2,
                   Q + (size_t)(b * T_ + t0 + r) * DQ_ + h * HD_ + seg * 8);
        cp_async16(kbase + (r * 72 + seg * 8) * 2,
                   Kp + (size_t)(b * S_ + s0 + r) * DQ_ + h * HD_ + seg * 8);
    }
    cp_commit();
    cp_wait0();
    __syncthreads();

    float acc[4][4][4];
    #pragma unroll
    for (int mt = 0; mt < 4; mt++)
        #pragma unroll
        for (int nt = 0; nt < 4; nt++)
            #pragma unroll
            for (int r = 0; r < 4; r++) acc[mt][nt][r] = 0.f;

    #pragma unroll
    for (int ks = 0; ks < 4; ks++) {
        const int kk = ks * 16;
        uint32_t a[4][4], bf[4][2];
        #pragma unroll
        for (int mt = 0; mt < 4; mt++) {
            int mr = wm + mt * 16;
            a[mt][0] = *(const uint32_t*)(Qs + (mr + g) * 72 + kk + 2 * tg);
            a[mt][1] = *(const uint32_t*)(Qs + (mr + g + 8) * 72 + kk + 2 * tg);
            a[mt][2] = *(const uint32_t*)(Qs + (mr + g) * 72 + kk + 8 + 2 * tg);
            a[mt][3] = *(const uint32_t*)(Qs + (mr + g + 8) * 72 + kk + 8 + 2 * tg);
        }
        #pragma unroll
        for (int nt = 0; nt < 4; nt++) {
            int nc = wn + nt * 8 + g;
            bf[nt][0] = *(const uint32_t*)(Ks + nc * 72 + kk + 2 * tg);
            bf[nt][1] = *(const uint32_t*)(Ks + nc * 72 + kk + 8 + 2 * tg);
        }
        #pragma unroll
        for (int mt = 0; mt < 4; mt++)
            #pragma unroll
            for (int nt = 0; nt < 4; nt++)
                mma_f16(acc[mt][nt], a[mt][0], a[mt][1], a[mt][2], a[mt][3],
                        bf[nt][0], bf[nt][1]);
    }

    __syncthreads();   // Q/K smem dead; E overlays it

    // Stage raw scaled scores to smem (STS.64, stride 136 -> conflict-free).
    #pragma unroll
    for (int mt = 0; mt < 4; mt++) {
        #pragma unroll
        for (int half = 0; half < 2; half++) {
            int rloc = wm + mt * 16 + half * 8 + g;
            #pragma unroll
            for (int nt = 0; nt < 4; nt++) {
                int sc = wn + nt * 8 + tg * 2;
                *(float2*)(Es + rloc * EPAD + sc) =
                    make_float2(acc[mt][nt][half * 2] * 0.125f,
                                acc[mt][nt][half * 2 + 1] * 0.125f);
            }
        }
    }
    __syncthreads();

    // Coalesced pass: mask + exp + write E; lane partial sums -> Ps.
    const int c4 = lane * 4;
    int4 kp = *(const int4*)(kpm + b * S_ + s0 + c4);
    float* arow = attn + ((size_t)bh * T_ + t0) * S_ + s0;
    #pragma unroll
    for (int rr = 0; rr < 16; rr++) {
        int r = wid + rr * 8;
        float4 e = *(const float4*)(Es + r * EPAD + c4);
        float4 m = *(const float4*)(attn_mask + (size_t)(t0 + r) * S_ + s0 + c4);
        float4 E;
        E.x = kp.x == 0 ? 0.f : __expf(e.x + m.x);
        E.y = kp.y == 0 ? 0.f : __expf(e.y + m.y);
        E.z = kp.z == 0 ? 0.f : __expf(e.z + m.z);
        E.w = kp.w == 0 ? 0.f : __expf(e.w + m.w);
        *(float4*)(arow + (size_t)r * S_ + c4) = E;
        Ps[r * PPAD + lane] = E.x + E.y + E.z + E.w;   // conflict-free STS.32
    }
    __syncthreads();

    // 128 threads each reduce one row: 8x LDS.128 + 31 FADD.
    if (tid < 128) {
        float s = 0.f;
        #pragma unroll
        for (int j = 0; j < 8; j++) {
            float4 v = *(const float4*)(Ps + tid * PPAD + j * 4);
            s += v.x + v.y + v.z + v.w;
        }
        psum[((size_t)bh * T_ + t0 + tid) * NSB + blockIdx.x] = s;
    }
}

// ---------------------------------------------------------------------------
// Combine partial sums: inv[row] = 1 / sum_i psum[row][i]
// ---------------------------------------------------------------------------
__global__ __launch_bounds__(256) void combine_inv(
    const float* __restrict__ psum, float* __restrict__ inv)
{
    int row = blockIdx.x * 256 + threadIdx.x;
    float s = 0.f;
    #pragma unroll
    for (int i = 0; i < NSB; i++) s += psum[(size_t)row * NSB + i];
    inv[row] = 1.0f / s;
}

// ---------------------------------------------------------------------------
// AV (fp16 mma) + fused normalize: p = E*inv written to attn via float4;
// fragment A loads fold inv into the f16 pack; ctx = p @ V.
// ---------------------------------------------------------------------------
__global__ __launch_bounds__(128, 4) void av_h(
    float* __restrict__ attn, const __half* __restrict__ Vt,
    const float* __restrict__ inv, float* __restrict__ ctx)
{
    extern __shared__ float dsm[];
    float* As = dsm;                                   // [2][128][40] fp32 (raw E)
    __half* Vs = (__half*)(dsm + 2 * 128 * 40);        // [2][64][40] half
    __shared__ float inv_s[128];
    const uint32_t abase = (uint32_t)__cvta_generic_to_shared(As);
    const uint32_t vbase = (uint32_t)__cvta_generic_to_shared(Vs);

    const int tid = threadIdx.x;
    const int wid = tid >> 5, lane = tid & 31;
    const int g = lane >> 2, tg = lane & 3;
    const int bh = blockIdx.y;
    const int t0 = blockIdx.x * 128;
    const int wm = (wid >> 1) * 64, wn = (wid & 1) * 32;

    float* arow = attn + ((size_t)bh * T_ + t0) * S_;
    const __half* vrow = Vt + (size_t)bh * HD_ * S_;

    if (tid < 128) inv_s[tid] = inv[(size_t)bh * T_ + t0 + tid];
    __syncthreads();

    float invA[4][2];
    #pragma unroll
    for (int mt = 0; mt < 4; mt++) {
        invA[mt][0] = inv_s[wm + mt * 16 + g];
        invA[mt][1] = inv_s[wm + mt * 16 + 8 + g];
    }

    float acc[4][4][4];
    #pragma unroll
    for (int mt = 0; mt < 4; mt++)
        #pragma unroll
        for (int nt = 0; nt < 4; nt++)
            #pragma unroll
            for (int r = 0; r < 4; r++) acc[mt][nt][r] = 0.f;

    auto load_stage = [&](int buf, int k0) {
        uint32_t ab = abase + (uint32_t)buf * 128 * 40 * 4;
        #pragma unroll
        for (int i = tid; i < 128 * 8; i += 128) {
            int r = i >> 3, seg = i & 7;
            cp_async16(ab + (r * 40 + seg * 4) * 4,
                       arow + (size_t)r * S_ + k0 + seg * 4);
        }
        uint32_t vb = vbase + (uint32_t)buf * 64 * 40 * 2;
        #pragma unroll
        for (int i = tid; i < 64 * 4; i += 128) {
            int r = i >> 2, seg = i & 3;
            cp_async16(vb + (r * 40 + seg * 8) * 2,
                       vrow + (size_t)r * S_ + k0 + seg * 8);
        }
        cp_commit();
    };

    load_stage(0, 0);
    int buf = 0;
    for (int k0 = 0; k0 < S_; k0 += 32, buf ^= 1) {
        cp_wait0();
        __syncthreads();
        if (k0 + 32 < S_) load_stage(buf ^ 1, k0 + 32);

        const float* Ab = As + buf * 128 * 40;
        const __half* Vb = Vs + buf * 64 * 40;

        // Fused normalize-write, vectorized: 8x (LDS.128 + 4 FMUL + STG.128).
        #pragma unroll
        for (int j = 0; j < 8; j++) {
            int chunk = tid + 128 * j;          // 0..1023
            int r = chunk >> 3, cq = chunk & 7;
            float4 e = *(const float4*)(Ab + r * 40 + cq * 4);
            float iv = inv_s[r];
            float4 p = make_float4(e.x * iv, e.y * iv, e.z * iv, e.w * iv);
            *(float4*)(arow + (size_t)r * S_ + k0 + cq * 4) = p;
        }

        #pragma unroll
        for (int ks = 0; ks < 2; ks++) {
            const int kk = ks * 16;
            uint32_t a[4][4], bf[4][2];
            #pragma unroll
            for (int mt = 0; mt < 4; mt++) {
                int mr = wm + mt * 16;
                float2 p0 = *(const float2*)(Ab + (mr + g) * 40 + kk + 2 * tg);
                float2 p1 = *(const float2*)(Ab + (mr + g + 8) * 40 + kk + 2 * tg);
                float2 p2 = *(const float2*)(Ab + (mr + g) * 40 + kk + 8 + 2 * tg);
                float2 p3 = *(const float2*)(Ab + (mr + g + 8) * 40 + kk + 8 + 2 * tg);
                float i0 = invA[mt][0], i1 = invA[mt][1];
                a[mt][0] = pack_h2(p0.x * i0, p0.y * i0);
                a[mt][1] = pack_h2(p1.x * i1, p1.y * i1);
                a[mt][2] = pack_h2(p2.x * i0, p2.y * i0);
                a[mt][3] = pack_h2(p3.x * i1, p3.y * i1);
            }
            #pragma unroll
            for (int nt = 0; nt < 4; nt++) {
                int nc = wn + nt * 8 + g;
                bf[nt][0] = *(const uint32_t*)(Vb + nc * 40 + kk + 2 * tg);
                bf[nt][1] = *(const uint32_t*)(Vb + nc * 40 + kk + 8 + 2 * tg);
            }
            #pragma unroll
            for (int mt = 0; mt < 4; mt++)
                #pragma unroll
                for (int nt = 0; nt < 4; nt++)
                    mma_f16(acc[mt][nt], a[mt][0], a[mt][1], a[mt][2], a[mt][3],
                            bf[nt][0], bf[nt][1]);
        }
        __syncthreads();
    }

    const int b = bh >> 3, h = bh & 7;
    #pragma unroll
    for (int mt = 0; mt < 4; mt++) {
        #pragma unroll
        for (int nt = 0; nt < 4; nt++) {
            int d0 = wn + nt * 8 + tg * 2;
            int t = t0 + wm + mt * 16 + g;
            ctx[(size_t)(b * T_ + t) * DQ_ + h * HD_ + d0]         = acc[mt][nt][0];
            ctx[(size_t)(b * T_ + t) * DQ_ + h * HD_ + d0 + 1]     = acc[mt][nt][1];
            ctx[(size_t)(b * T_ + t + 8) * DQ_ + h * HD_ + d0]     = acc[mt][nt][2];
            ctx[(size_t)(b * T_ + t + 8) * DQ_ + h * HD_ + d0 + 1] = acc[mt][nt][3];
        }
    }
}

// ---------------------------------------------------------------------------
// Launch (single stream)
// ---------------------------------------------------------------------------
extern "C" void kernel_launch(void* const* d_in, const int* in_sizes, int n_in,
                              void* d_out, int out_size)
{
    const float* query     = (const float*)d_in[0];
    const float* key       = (const float*)d_in[1];
    const float* value     = (const float*)d_in[2];
    const int*   kpm       = (const int*)  d_in[3];
    const float* attn_mask = (const float*)d_in[4];
    const float* Wq = (const float*)d_in[5];
    const float* bq = (const float*)d_in[6];
    const float* Wk = (const float*)d_in[7];
    const float* bk = (const float*)d_in[8];
    const float* Wv = (const float*)d_in[9];
    const float* bv = (const float*)d_in[10];
    const float* Wo = (const float*)d_in[11];
    const float* bo = (const float*)d_in[12];

    float* out  = (float*)d_out;                        // [B,T,DQ]
    float* attn = out + (size_t)B_ * T_ * DQ_;          // [B,H,T,S]

    __half *Qh, *Kh, *Vt;
    float *Cp, *Ps, *Iv;
    cudaGetSymbolAddress((void**)&Qh, g_Qh);
    cudaGetSymbolAddress((void**)&Kh, g_Kh);
    cudaGetSymbolAddress((void**)&Vt, g_Vt);
    cudaGetSymbolAddress((void**)&Cp, g_ctx);
    cudaGetSymbolAddress((void**)&Ps, g_psum);
    cudaGetSymbolAddress((void**)&Iv, g_inv);

    const int GEMM_SMEM  = (2 * 128 * 36 + 2 * 32 * 68) * 4;        // 54272
    const int AV_SMEM    = 2 * 128 * 40 * 4 + 2 * 64 * 40 * 2;      // 51200
    const int SCORE_SMEM = (128 * EPAD + 128 * PPAD) * 4;            // 88064

    static int attr_done = 0;
    if (!attr_done) {
        cudaFuncSetAttribute(gemm_bias_tc<0>, cudaFuncAttributeMaxDynamicSharedMemorySize, GEMM_SMEM);
        cudaFuncSetAttribute(gemm_bias_tc<1>, cudaFuncAttributeMaxDynamicSharedMemorySize, GEMM_SMEM);
        cudaFuncSetAttribute(gemm_bias_tc<2>, cudaFuncAttributeMaxDynamicSharedMemorySize, GEMM_SMEM);
        cudaFuncSetAttribute(score_h,         cudaFuncAttributeMaxDynamicSharedMemorySize, SCORE_SMEM);
        cudaFuncSetAttribute(av_h,            cudaFuncAttributeMaxDynamicSharedMemorySize, AV_SMEM);
        attr_done = 1;
    }

    const int M = B_ * T_;   // 8192

    // Projections: Q,K -> half; V -> half transposed
    gemm_bias_tc<1><<<dim3(DQ_ / 64, M / 128), 128, GEMM_SMEM>>>(query, Wq, bq, Qh, M, DQ_, DQ_);
    gemm_bias_tc<1><<<dim3(DQ_ / 64, M / 128), 128, GEMM_SMEM>>>(key,   Wk, bk, Kh, M, DQ_, DKV_);
    gemm_bias_tc<2><<<dim3(DQ_ / 64, M / 128), 128, GEMM_SMEM>>>(value, Wv, bv, Vt, M, DQ_, DKV_);

    // E = exp(scores) + per-row partial sums (fp16 mma, coalesced fused epilogue)
    score_h<<<dim3(S_ / 128, T_ / 128, B_ * H_), 256, SCORE_SMEM>>>(Qh, Kh, attn_mask, kpm, attn, Ps);

    // inv[row] = 1 / row sum
    combine_inv<<<(B_ * H_ * T_) / 256, 256>>>(Ps, Iv);

    // p = E*inv -> attn; ctx = p @ V (fp16 mma)
    av_h<<<dim3(T_ / 128, B_ * H_), 128, AV_SMEM>>>(attn, Vt, Iv, Cp);

    // Output projection (fp32 out)
    gemm_bias_tc<0><<<dim3(DQ_ / 64, M / 128), 128, GEMM_SMEM>>>(Cp, Wo, bo, out, M, DQ_, DQ_);
}

// round 16
// speedup vs baseline: 1.2627x; 1.2627x over previous
#include <cuda_runtime.h>
#include <cuda_fp16.h>
#include <math.h>
#include <stdint.h>

// Problem constants
#define B_   4
#define T_   2048
#define S_   2048
#define DQ_  512
#define DKV_ 1024
#define H_   8
#define HD_  64

// Scratch buffers (allocation-free: __device__ globals)
__device__ __half g_qin[B_ * T_ * DQ_];             // query in half
__device__ __half g_kin[B_ * S_ * DKV_];            // key in half
__device__ __half g_vin[B_ * S_ * DKV_];            // value in half
__device__ __half g_Wqt[DQ_ * DQ_];                 // Wq^T [N][K] half
__device__ __half g_Wkt[DQ_ * DKV_];                // Wk^T [512][1024]
__device__ __half g_Wvt[DQ_ * DKV_];                // Wv^T [512][1024]
__device__ __half g_Wot[DQ_ * DQ_];                 // Wo^T [512][512]
__device__ __half g_Qh[B_ * T_ * DQ_];              // Q proj half
__device__ __half g_Kh[B_ * S_ * DQ_];              // K proj half
__device__ __half g_Vt[B_ * H_ * HD_ * (size_t)S_]; // V transposed [b,h,d,s] half
__device__ __half g_ctxh[B_ * T_ * DQ_];            // ctx half

// ---------------------------------------------------------------------------
// Helpers
// ---------------------------------------------------------------------------
__device__ __forceinline__ uint32_t pack_h2(float lo, float hi) {
    uint32_t r;
    asm("cvt.rn.f16x2.f32 %0, %1, %2;" : "=r"(r) : "f"(hi), "f"(lo));
    return r;
}

__device__ __forceinline__ void mma_f16(float d[4],
                                        uint32_t a0, uint32_t a1, uint32_t a2, uint32_t a3,
                                        uint32_t b0, uint32_t b1) {
    asm volatile(
        "mma.sync.aligned.m16n8k16.row.col.f32.f16.f16.f32 "
        "{%0,%1,%2,%3}, {%4,%5,%6,%7}, {%8,%9}, {%0,%1,%2,%3};\n"
        : "+f"(d[0]), "+f"(d[1]), "+f"(d[2]), "+f"(d[3])
        : "r"(a0), "r"(a1), "r"(a2), "r"(a3), "r"(b0), "r"(b1));
}

__device__ __forceinline__ void cp_async16(uint32_t s, const void* g) {
    asm volatile("cp.async.cg.shared.global [%0], [%1], 16;\n" :: "r"(s), "l"(g));
}
__device__ __forceinline__ void cp_commit() { asm volatile("cp.async.commit_group;\n" ::: "memory"); }
__device__ __forceinline__ void cp_wait0()  { asm volatile("cp.async.wait_group 0;\n" ::: "memory"); }

// ---------------------------------------------------------------------------
// fp32 -> half (vectorized)
// ---------------------------------------------------------------------------
__global__ __launch_bounds__(256) void cvt_f2h(
    const float* __restrict__ src, __half* __restrict__ dst, int n)
{
    int i = (blockIdx.x * 256 + threadIdx.x) * 4;
    if (i < n) {
        float4 v = *(const float4*)(src + i);
        __half2* d = (__half2*)(dst + i);
        d[0] = __floats2half2_rn(v.x, v.y);
        d[1] = __floats2half2_rn(v.z, v.w);
    }
}

// ---------------------------------------------------------------------------
// W [K][N] fp32 -> Wt [N][K] half (smem tile transpose)
// ---------------------------------------------------------------------------
__global__ __launch_bounds__(256) void cvt_tr(
    const float* __restrict__ W, __half* __restrict__ Wt, int K, int N)
{
    __shared__ float tile[32][33];
    int k0 = blockIdx.y * 32, n0 = blockIdx.x * 32;
    int tx = threadIdx.x & 31, ty = threadIdx.x >> 5;   // (32, 8)
    #pragma unroll
    for (int j = ty; j < 32; j += 8)
        tile[j][tx] = W[(size_t)(k0 + j) * N + n0 + tx];
    __syncthreads();
    #pragma unroll
    for (int j = ty; j < 32; j += 8)
        Wt[(size_t)(n0 + j) * K + k0 + tx] = __float2half(tile[tx][j]);
}

// ---------------------------------------------------------------------------
// All-half GEMM: C[M,N] = A[M,K] @ Wt[N,K]^T + bias[N]
// Block 128x64, 4 warps (2x2), BK=64, cp.async double-buffered, fp16 mma.
// MODE 0: fp32 out. MODE 1: half out. MODE 2: half out, Vt layout.
// smem: A [2][128][72] half + B [2][64][72] half = 55296 B.
// ---------------------------------------------------------------------------
template <int MODE>
__global__ __launch_bounds__(128, 4) void gemm_h(
    const __half* __restrict__ A, const __half* __restrict__ Wt,
    const float* __restrict__ bias, void* __restrict__ Cout,
    int M, int N, int K)
{
    extern __shared__ __half hsm[];
    __half* As = hsm;                 // [2][128][72]
    __half* Bs = hsm + 2 * 128 * 72;  // [2][64][72]
    const uint32_t abase = (uint32_t)__cvta_generic_to_shared(As);
    const uint32_t bbase = (uint32_t)__cvta_generic_to_shared(Bs);

    const int tid = threadIdx.x;
    const int wid = tid >> 5, lane = tid & 31;
    const int g = lane >> 2, tg = lane & 3;
    const int bm = blockIdx.y * 128, bn = blockIdx.x * 64;
    const int wm = (wid >> 1) * 64, wn = (wid & 1) * 32;

    float acc[4][4][4];
    #pragma unroll
    for (int mt = 0; mt < 4; mt++)
        #pragma unroll
        for (int nt = 0; nt < 4; nt++)
            #pragma unroll
            for (int r = 0; r < 4; r++) acc[mt][nt][r] = 0.f;

    auto load_stage = [&](int buf, int k0) {
        uint32_t ab = abase + (uint32_t)buf * 128 * 72 * 2;
        #pragma unroll
        for (int i = tid; i < 128 * 8; i += 128) {     // A: 128 rows x 128B
            int r = i >> 3, seg = i & 7;
            cp_async16(ab + (r * 72 + seg * 8) * 2,
                       A + (size_t)(bm + r) * K + k0 + seg * 8);
        }
        uint32_t bb = bbase + (uint32_t)buf * 64 * 72 * 2;
        #pragma unroll
        for (int i = tid; i < 64 * 8; i += 128) {      // B: 64 n-rows x 128B
            int r = i >> 3, seg = i & 7;
            cp_async16(bb + (r * 72 + seg * 8) * 2,
                       Wt + (size_t)(bn + r) * K + k0 + seg * 8);
        }
        cp_commit();
    };

    load_stage(0, 0);
    int buf = 0;
    for (int k0 = 0; k0 < K; k0 += 64, buf ^= 1) {
        cp_wait0();
        __syncthreads();
        if (k0 + 64 < K) load_stage(buf ^ 1, k0 + 64);

        const __half* Ab = As + buf * 128 * 72;
        const __half* Bb = Bs + buf * 64 * 72;
        #pragma unroll
        for (int ks = 0; ks < 4; ks++) {
            const int kk = ks * 16;
            uint32_t a[4][4], bf[4][2];
            #pragma unroll
            for (int mt = 0; mt < 4; mt++) {
                int mr = wm + mt * 16;
                a[mt][0] = *(const uint32_t*)(Ab + (mr + g) * 72 + kk + 2 * tg);
                a[mt][1] = *(const uint32_t*)(Ab + (mr + g + 8) * 72 + kk + 2 * tg);
                a[mt][2] = *(const uint32_t*)(Ab + (mr + g) * 72 + kk + 8 + 2 * tg);
                a[mt][3] = *(const uint32_t*)(Ab + (mr + g + 8) * 72 + kk + 8 + 2 * tg);
            }
            #pragma unroll
            for (int nt = 0; nt < 4; nt++) {
                int nc = wn + nt * 8 + g;
                bf[nt][0] = *(const uint32_t*)(Bb + nc * 72 + kk + 2 * tg);
                bf[nt][1] = *(const uint32_t*)(Bb + nc * 72 + kk + 8 + 2 * tg);
            }
            #pragma unroll
            for (int mt = 0; mt < 4; mt++)
                #pragma unroll
                for (int nt = 0; nt < 4; nt++)
                    mma_f16(acc[mt][nt], a[mt][0], a[mt][1], a[mt][2], a[mt][3],
                            bf[nt][0], bf[nt][1]);
        }
    }

    #pragma unroll
    for (int mt = 0; mt < 4; mt++) {
        #pragma unroll
        for (int nt = 0; nt < 4; nt++) {
            int n0 = bn + wn + nt * 8 + tg * 2;
            float b0v = bias[n0], b1v = bias[n0 + 1];
            int r0 = bm + wm + mt * 16 + g;
            float v00 = acc[mt][nt][0] + b0v, v01 = acc[mt][nt][1] + b1v;
            float v10 = acc[mt][nt][2] + b0v, v11 = acc[mt][nt][3] + b1v;
            if (MODE == 0) {
                float* C = (float*)Cout;
                C[(size_t)r0 * N + n0]           = v00;
                C[(size_t)r0 * N + n0 + 1]       = v01;
                C[(size_t)(r0 + 8) * N + n0]     = v10;
                C[(size_t)(r0 + 8) * N + n0 + 1] = v11;
            } else if (MODE == 1) {
                __half* C = (__half*)Cout;
                C[(size_t)r0 * N + n0]           = __float2half(v00);
                C[(size_t)r0 * N + n0 + 1]       = __float2half(v01);
                C[(size_t)(r0 + 8) * N + n0]     = __float2half(v10);
                C[(size_t)(r0 + 8) * N + n0 + 1] = __float2half(v11);
            } else {
                __half* C = (__half*)Cout;
                int h0 = n0 >> 6, d0 = n0 & 63;
                int b0i = r0 >> 11, t0i = r0 & 2047;
                size_t base0 = ((size_t)(b0i * 8 + h0) * 64 + d0) * 2048;
                C[base0 + t0i]            = __float2half(v00);
                C[base0 + 2048 + t0i]     = __float2half(v01);
                C[base0 + t0i + 8]        = __float2half(v10);
                C[base0 + 2048 + t0i + 8] = __float2half(v11);
            }
        }
    }
}

// ---------------------------------------------------------------------------
// Scores (fp16 mma): attn[b,h,t,s] = (Q.K)/8 + mask, kpm==0 -> -inf   (R12)
// ---------------------------------------------------------------------------
#define EPAD 136

__global__ __launch_bounds__(256, 2) void score_h(
    const __half* __restrict__ Q, const __half* __restrict__ Kp,
    const float* __restrict__ attn_mask, const int* __restrict__ kpm,
    float* __restrict__ attn)
{
    extern __shared__ float dsm[];
    __half* Qs = (__half*)dsm;            // [128][72] half
    __half* Ks = Qs + 128 * 72;           // [128][72] half
    float*  Es = dsm;                     // [128][136] fp32 (overlays Q/K)
    const uint32_t qbase = (uint32_t)__cvta_generic_to_shared(Qs);
    const uint32_t kbase = (uint32_t)__cvta_generic_to_shared(Ks);

    const int tid = threadIdx.x;
    const int wid = tid >> 5, lane = tid & 31;
    const int g = lane >> 2, tg = lane & 3;
    const int bh = blockIdx.z;
    const int b = bh >> 3, h = bh & 7;
    const int t0 = blockIdx.y * 128, s0 = blockIdx.x * 128;
    const int wm = (wid >> 2) * 64, wn = (wid & 3) * 32;

    #pragma unroll
    for (int i = tid; i < 128 * 8; i += 256) {
        int r = i >> 3, seg = i & 7;
        cp_async16(qbase + (r * 72 + seg * 8) * 2,
                   Q + (size_t)(b * T_ + t0 + r) * DQ_ + h * HD_ + seg * 8);
        cp_async16(kbase + (r * 72 + seg * 8) * 2,
                   Kp + (size_t)(b * S_ + s0 + r) * DQ_ + h * HD_ + seg * 8);
    }
    cp_commit();
    cp_wait0();
    __syncthreads();

    float acc[4][4][4];
    #pragma unroll
    for (int mt = 0; mt < 4; mt++)
        #pragma unroll
        for (int nt = 0; nt < 4; nt++)
            #pragma unroll
            for (int r = 0; r < 4; r++) acc[mt][nt][r] = 0.f;

    #pragma unroll
    for (int ks = 0; ks < 4; ks++) {
        const int kk = ks * 16;
        uint32_t a[4][4], bf[4][2];
        #pragma unroll
        for (int mt = 0; mt < 4; mt++) {
            int mr = wm + mt * 16;
            a[mt][0] = *(const uint32_t*)(Qs + (mr + g) * 72 + kk + 2 * tg);
            a[mt][1] = *(const uint32_t*)(Qs + (mr + g + 8) * 72 + kk + 2 * tg);
            a[mt][2] = *(const uint32_t*)(Qs + (mr + g) * 72 + kk + 8 + 2 * tg);
            a[mt][3] = *(const uint32_t*)(Qs + (mr + g + 8) * 72 + kk + 8 + 2 * tg);
        }
        #pragma unroll
        for (int nt = 0; nt < 4; nt++) {
            int nc = wn + nt * 8 + g;
            bf[nt][0] = *(const uint32_t*)(Ks + nc * 72 + kk + 2 * tg);
            bf[nt][1] = *(const uint32_t*)(Ks + nc * 72 + kk + 8 + 2 * tg);
        }
        #pragma unroll
        for (int mt = 0; mt < 4; mt++)
            #pragma unroll
            for (int nt = 0; nt < 4; nt++)
                mma_f16(acc[mt][nt], a[mt][0], a[mt][1], a[mt][2], a[mt][3],
                        bf[nt][0], bf[nt][1]);
    }

    __syncthreads();   // Q/K smem dead; E overlays it

    #pragma unroll
    for (int mt = 0; mt < 4; mt++) {
        #pragma unroll
        for (int half = 0; half < 2; half++) {
            int rloc = wm + mt * 16 + half * 8 + g;
            #pragma unroll
            for (int nt = 0; nt < 4; nt++) {
                int sc = wn + nt * 8 + tg * 2;
                *(float2*)(Es + rloc * EPAD + sc) =
                    make_float2(acc[mt][nt][half * 2] * 0.125f,
                                acc[mt][nt][half * 2 + 1] * 0.125f);
            }
        }
    }
    __syncthreads();

    const int c4 = lane * 4;
    int4 kp = *(const int4*)(kpm + b * S_ + s0 + c4);
    float4 nif = make_float4(kp.x == 0 ? -INFINITY : 0.f,
                             kp.y == 0 ? -INFINITY : 0.f,
                             kp.z == 0 ? -INFINITY : 0.f,
                             kp.w == 0 ? -INFINITY : 0.f);
    float* arow = attn + ((size_t)bh * T_ + t0) * S_ + s0;
    #pragma unroll
    for (int rr = 0; rr < 16; rr++) {
        int r = wid + rr * 8;
        float4 e = *(const float4*)(Es + r * EPAD + c4);
        float4 m = *(const float4*)(attn_mask + (size_t)(t0 + r) * S_ + s0 + c4);
        float4 v;
        v.x = kp.x == 0 ? nif.x : e.x + m.x;
        v.y = kp.y == 0 ? nif.y : e.y + m.y;
        v.z = kp.z == 0 ? nif.z : e.z + m.z;
        v.w = kp.w == 0 ? nif.w : e.w + m.w;
        *(float4*)(arow + (size_t)r * S_ + c4) = v;
    }
}

// ---------------------------------------------------------------------------
// In-place row softmax over S=2048 (proven).
// ---------------------------------------------------------------------------
__global__ __launch_bounds__(256) void softmax_kernel(float* __restrict__ attn)
{
    size_t row = blockIdx.x;
    float* p = attn + row * (size_t)S_;
    int tid = threadIdx.x;

    float v[8];
    #pragma unroll
    for (int i = 0; i < 8; i++) v[i] = p[tid + 256 * i];

    float m = v[0];
    #pragma unroll
    for (int i = 1; i < 8; i++) m = fmaxf(m, v[i]);
    #pragma unroll
    for (int o = 16; o > 0; o >>= 1) m = fmaxf(m, __shfl_xor_sync(0xffffffffu, m, o));

    __shared__ float red[8];
    if ((tid & 31) == 0) red[tid >> 5] = m;
    __syncthreads();
    if (tid < 32) {
        float x = (tid < 8) ? red[tid] : -INFINITY;
        #pragma unroll
        for (int o = 4; o > 0; o >>= 1) x = fmaxf(x, __shfl_xor_sync(0xffffffffu, x, o));
        if (tid == 0) red[0] = x;
    }
    __syncthreads();
    m = red[0];
    __syncthreads();

    float s = 0.f;
    #pragma unroll
    for (int i = 0; i < 8; i++) { v[i] = __expf(v[i] - m); s += v[i]; }
    #pragma unroll
    for (int o = 16; o > 0; o >>= 1) s += __shfl_xor_sync(0xffffffffu, s, o);
    if ((tid & 31) == 0) red[tid >> 5] = s;
    __syncthreads();
    if (tid < 32) {
        float x = (tid < 8) ? red[tid] : 0.f;
        #pragma unroll
        for (int o = 4; o > 0; o >>= 1) x += __shfl_xor_sync(0xffffffffu, x, o);
        if (tid == 0) red[0] = x;
    }
    __syncthreads();
    float inv = 1.0f / red[0];

    #pragma unroll
    for (int i = 0; i < 8; i++) p[tid + 256 * i] = v[i] * inv;
}

// ---------------------------------------------------------------------------
// AV (fp16 mma, R12 mainloop): ctx(HALF)[b,t,h,:] = attn[b,h,t,:] @ V
// ---------------------------------------------------------------------------
__global__ __launch_bounds__(128, 4) void av_h(
    const float* __restrict__ attn, const __half* __restrict__ Vt,
    __half* __restrict__ ctxh)
{
    extern __shared__ float dsm[];
    float* As = dsm;                                   // [2][128][40] fp32
    __half* Vs = (__half*)(dsm + 2 * 128 * 40);        // [2][64][40] half
    const uint32_t abase = (uint32_t)__cvta_generic_to_shared(As);
    const uint32_t vbase = (uint32_t)__cvta_generic_to_shared(Vs);

    const int tid = threadIdx.x;
    const int wid = tid >> 5, lane = tid & 31;
    const int g = lane >> 2, tg = lane & 3;
    const int bh = blockIdx.y;
    const int t0 = blockIdx.x * 128;
    const int wm = (wid >> 1) * 64, wn = (wid & 1) * 32;

    const float* arow = attn + ((size_t)bh * T_ + t0) * S_;
    const __half* vrow = Vt + (size_t)bh * HD_ * S_;

    float acc[4][4][4];
    #pragma unroll
    for (int mt = 0; mt < 4; mt++)
        #pragma unroll
        for (int nt = 0; nt < 4; nt++)
            #pragma unroll
            for (int r = 0; r < 4; r++) acc[mt][nt][r] = 0.f;

    auto load_stage = [&](int buf, int k0) {
        uint32_t ab = abase + (uint32_t)buf * 128 * 40 * 4;
        #pragma unroll
        for (int i = tid; i < 128 * 8; i += 128) {
            int r = i >> 3, seg = i & 7;
            cp_async16(ab + (r * 40 + seg * 4) * 4,
                       arow + (size_t)r * S_ + k0 + seg * 4);
        }
        uint32_t vb = vbase + (uint32_t)buf * 64 * 40 * 2;
        #pragma unroll
        for (int i = tid; i < 64 * 4; i += 128) {
            int r = i >> 2, seg = i & 3;
            cp_async16(vb + (r * 40 + seg * 8) * 2,
                       vrow + (size_t)r * S_ + k0 + seg * 8);
        }
        cp_commit();
    };

    load_stage(0, 0);
    int buf = 0;
    for (int k0 = 0; k0 < S_; k0 += 32, buf ^= 1) {
        cp_wait0();
        __syncthreads();
        if (k0 + 32 < S_) load_stage(buf ^ 1, k0 + 32);

        const float* Ab = As + buf * 128 * 40;
        const __half* Vb = Vs + buf * 64 * 40;
        #pragma unroll
        for (int ks = 0; ks < 2; ks++) {
            const int kk = ks * 16;
            uint32_t a[4][4], bf[4][2];
            #pragma unroll
            for (int mt = 0; mt < 4; mt++) {
                int mr = wm + mt * 16;
                float2 p0 = *(const float2*)(Ab + (mr + g) * 40 + kk + 2 * tg);
                float2 p1 = *(const float2*)(Ab + (mr + g + 8) * 40 + kk + 2 * tg);
                float2 p2 = *(const float2*)(Ab + (mr + g) * 40 + kk + 8 + 2 * tg);
                float2 p3 = *(const float2*)(Ab + (mr + g + 8) * 40 + kk + 8 + 2 * tg);
                a[mt][0] = pack_h2(p0.x, p0.y);
                a[mt][1] = pack_h2(p1.x, p1.y);
                a[mt][2] = pack_h2(p2.x, p2.y);
                a[mt][3] = pack_h2(p3.x, p3.y);
            }
            #pragma unroll
            for (int nt = 0; nt < 4; nt++) {
                int nc = wn + nt * 8 + g;
                bf[nt][0] = *(const uint32_t*)(Vb + nc * 40 + kk + 2 * tg);
                bf[nt][1] = *(const uint32_t*)(Vb + nc * 40 + kk + 8 + 2 * tg);
            }
            #pragma unroll
            for (int mt = 0; mt < 4; mt++)
                #pragma unroll
                for (int nt = 0; nt < 4; nt++)
                    mma_f16(acc[mt][nt], a[mt][0], a[mt][1], a[mt][2], a[mt][3],
                            bf[nt][0], bf[nt][1]);
        }
        __syncthreads();
    }

    const int b = bh >> 3, h = bh & 7;
    #pragma unroll
    for (int mt = 0; mt < 4; mt++) {
        #pragma unroll
        for (int nt = 0; nt < 4; nt++) {
            int d0 = wn + nt * 8 + tg * 2;
            int t = t0 + wm + mt * 16 + g;
            ctxh[(size_t)(b * T_ + t) * DQ_ + h * HD_ + d0]         = __float2half(acc[mt][nt][0]);
            ctxh[(size_t)(b * T_ + t) * DQ_ + h * HD_ + d0 + 1]     = __float2half(acc[mt][nt][1]);
            ctxh[(size_t)(b * T_ + t + 8) * DQ_ + h * HD_ + d0]     = __float2half(acc[mt][nt][2]);
            ctxh[(size_t)(b * T_ + t + 8) * DQ_ + h * HD_ + d0 + 1] = __float2half(acc[mt][nt][3]);
        }
    }
}

// ---------------------------------------------------------------------------
// Launch (single stream)
// ---------------------------------------------------------------------------
extern "C" void kernel_launch(void* const* d_in, const int* in_sizes, int n_in,
                              void* d_out, int out_size)
{
    const float* query     = (const float*)d_in[0];
    const float* key       = (const float*)d_in[1];
    const float* value     = (const float*)d_in[2];
    const int*   kpm       = (const int*)  d_in[3];
    const float* attn_mask = (const float*)d_in[4];
    const float* Wq = (const float*)d_in[5];
    const float* bq = (const float*)d_in[6];
    const float* Wk = (const float*)d_in[7];
    const float* bk = (const float*)d_in[8];
    const float* Wv = (const float*)d_in[9];
    const float* bv = (const float*)d_in[10];
    const float* Wo = (const float*)d_in[11];
    const float* bo = (const float*)d_in[12];

    float* out  = (float*)d_out;                        // [B,T,DQ]
    float* attn = out + (size_t)B_ * T_ * DQ_;          // [B,H,T,S]

    __half *qin, *kin, *vin, *Wqt, *Wkt, *Wvt, *Wot, *Qh, *Kh, *Vt, *ctxh;
    cudaGetSymbolAddress((void**)&qin, g_qin);
    cudaGetSymbolAddress((void**)&kin, g_kin);
    cudaGetSymbolAddress((void**)&vin, g_vin);
    cudaGetSymbolAddress((void**)&Wqt, g_Wqt);
    cudaGetSymbolAddress((void**)&Wkt, g_Wkt);
    cudaGetSymbolAddress((void**)&Wvt, g_Wvt);
    cudaGetSymbolAddress((void**)&Wot, g_Wot);
    cudaGetSymbolAddress((void**)&Qh, g_Qh);
    cudaGetSymbolAddress((void**)&Kh, g_Kh);
    cudaGetSymbolAddress((void**)&Vt, g_Vt);
    cudaGetSymbolAddress((void**)&ctxh, g_ctxh);

    const int GEMMH_SMEM = (2 * 128 * 72 + 2 * 64 * 72) * 2;   // 55296
    const int AV_SMEM    = 2 * 128 * 40 * 4 + 2 * 64 * 40 * 2; // 51200
    const int SCORE_SMEM = 128 * EPAD * 4;                      // 69632

    static int attr_done = 0;
    if (!attr_done) {
        cudaFuncSetAttribute(gemm_h<0>, cudaFuncAttributeMaxDynamicSharedMemorySize, GEMMH_SMEM);
        cudaFuncSetAttribute(gemm_h<1>, cudaFuncAttributeMaxDynamicSharedMemorySize, GEMMH_SMEM);
        cudaFuncSetAttribute(gemm_h<2>, cudaFuncAttributeMaxDynamicSharedMemorySize, GEMMH_SMEM);
        cudaFuncSetAttribute(score_h,   cudaFuncAttributeMaxDynamicSharedMemorySize, SCORE_SMEM);
        cudaFuncSetAttribute(av_h,      cudaFuncAttributeMaxDynamicSharedMemorySize, AV_SMEM);
        attr_done = 1;
    }

    const int M = B_ * T_;   // 8192

    // Convert inputs and weights to half (weights transposed)
    cvt_f2h<<<(M * DQ_ / 4 + 255) / 256, 256>>>(query, qin, M * DQ_);
    cvt_f2h<<<(M * DKV_ / 4 + 255) / 256, 256>>>(key,   kin, M * DKV_);
    cvt_f2h<<<(M * DKV_ / 4 + 255) / 256, 256>>>(value, vin, M * DKV_);
    cvt_tr<<<dim3(DQ_ / 32, DQ_ / 32),  256>>>(Wq, Wqt, DQ_,  DQ_);
    cvt_tr<<<dim3(DQ_ / 32, DKV_ / 32), 256>>>(Wk, Wkt, DKV_, DQ_);
    cvt_tr<<<dim3(DQ_ / 32, DKV_ / 32), 256>>>(Wv, Wvt, DKV_, DQ_);
    cvt_tr<<<dim3(DQ_ / 32, DQ_ / 32),  256>>>(Wo, Wot, DQ_,  DQ_);

    // Projections (all-half fp16 mma)
    gemm_h<1><<<dim3(DQ_ / 64, M / 128), 128, GEMMH_SMEM>>>(qin, Wqt, bq, Qh, M, DQ_, DQ_);
    gemm_h<1><<<dim3(DQ_ / 64, M / 128), 128, GEMMH_SMEM>>>(kin, Wkt, bk, Kh, M, DQ_, DKV_);
    gemm_h<2><<<dim3(DQ_ / 64, M / 128), 128, GEMMH_SMEM>>>(vin, Wvt, bv, Vt, M, DQ_, DKV_);

    // Scores + mask -> attn region of d_out
    score_h<<<dim3(S_ / 128, T_ / 128, B_ * H_), 256, SCORE_SMEM>>>(Qh, Kh, attn_mask, kpm, attn);

    // Row softmax in place
    softmax_kernel<<<B_ * H_ * T_, 256>>>(attn);

    // attn @ V -> ctx (half)
    av_h<<<dim3(T_ / 128, B_ * H_), 128, AV_SMEM>>>(attn, Vt, ctxh);

    // Output projection (fp32 out)
    gemm_h<0><<<dim3(DQ_ / 64, M / 128), 128, GEMMH_SMEM>>>(ctxh, Wot, bo, out, M, DQ_, DQ_);
}